// round 1
// baseline (speedup 1.0000x reference)
#include <cuda_runtime.h>
#include <cstddef>

// Problem constants (fixed by the dataset)
constexpr int N_ATOMS  = 100000;
constexpr int N_BONDS  = 200001;
constexpr int ATOM_FDIM = 39;
constexpr int BOND_FDIM = 11;
constexpr int IN_FDIM   = ATOM_FDIM + BOND_FDIM;   // 50
constexpr int OUT_FDIM  = ATOM_FDIM + 256;         // 295
constexpr int MAX_NB   = 6;
constexpr int HIDDEN   = 256;
constexpr int N_MOLS   = 2000;
constexpr int APM      = N_ATOMS / N_MOLS;         // 50

// Scratch (device globals: allocation-free per harness rules)
__device__ float g_binput[(size_t)N_BONDS * HIDDEN];
__device__ float g_msg0  [(size_t)N_BONDS * HIDDEN];
__device__ float g_msg1  [(size_t)N_BONDS * HIDDEN];
__device__ float g_nei   [(size_t)N_BONDS * HIDDEN];
__device__ float g_anei  [(size_t)N_ATOMS * HIDDEN];
__device__ float g_atomh [(size_t)N_ATOMS * HIDDEN];

// ---------------------------------------------------------------------------
// Mode-specialized operand fetch for the shared SGEMM core.
// MODE 0: init    A = fbonds [M,50],                       W = W_i [256,50]
// MODE 1: round   A = nei    [M,256],                      W = W_h [256,256]
// MODE 2: readout A = concat(fatoms[M,39], anei[M,256]),   W = W_o [256,295]
// ---------------------------------------------------------------------------
template <int MODE>
__device__ __forceinline__ float fetchA(const float* __restrict__ A1,
                                        const float* __restrict__ A2,
                                        int row, int kg, int M) {
    if (row >= M) return 0.0f;
    if (MODE == 0) {
        return (kg < IN_FDIM) ? A1[(size_t)row * IN_FDIM + kg] : 0.0f;
    } else if (MODE == 1) {
        return A1[(size_t)row * HIDDEN + kg];
    } else {
        if (kg < ATOM_FDIM)  return A1[(size_t)row * ATOM_FDIM + kg];
        if (kg < OUT_FDIM)   return A2[(size_t)row * HIDDEN + (kg - ATOM_FDIM)];
        return 0.0f;
    }
}

template <int MODE>
__device__ __forceinline__ float fetchB(const float* __restrict__ W, int n, int kg) {
    if (MODE == 0) {
        return (kg < IN_FDIM) ? W[(size_t)n * IN_FDIM + kg] : 0.0f;
    } else if (MODE == 1) {
        return W[(size_t)n * HIDDEN + kg];
    } else {
        return (kg < OUT_FDIM) ? W[(size_t)n * OUT_FDIM + kg] : 0.0f;
    }
}

// ---------------------------------------------------------------------------
// SGEMM: C[M,256] = epilogue( A[M,K] @ W[256,K]^T )
// BM=128, BN=256 (full N -> A streamed exactly once), BK=8, 512 threads,
// 8x8 register microtile per thread, double-buffered smem.
//   MODE 0: C2 <- raw (binput), C <- relu(raw)
//   MODE 1: C  <- relu(extra(binput) + raw)
//   MODE 2: C  <- relu(raw + extra(b_o))
// ---------------------------------------------------------------------------
template <int MODE, int KP>
__global__ void __launch_bounds__(512, 1)
gemm_k(const float* __restrict__ A1, const float* __restrict__ A2,
       const float* __restrict__ W,  const float* __restrict__ extra,
       float* __restrict__ C, float* __restrict__ C2, int M) {
    // padded strides (132/260) make the staging stores bank-conflict-free
    __shared__ __align__(16) float As[2][8][132];
    __shared__ __align__(16) float Bs[2][8][260];

    const int tid = threadIdx.x;
    const int tx  = tid & 31;   // column group: cols tx*8 .. tx*8+7
    const int ty  = tid >> 5;   // row group:    rows ty*8 .. ty*8+7
    const int mBlock = blockIdx.y * 128;

    const int ka = tid & 7;     // k within tile for staging
    const int ra = tid >> 3;    // 0..63

    float acc[8][8];
#pragma unroll
    for (int i = 0; i < 8; ++i)
#pragma unroll
        for (int j = 0; j < 8; ++j) acc[i][j] = 0.0f;

    float pa0, pa1, pb0, pb1, pb2, pb3;

    // --- stage tile 0 ---
    {
        const int kg = ka;
        pa0 = fetchA<MODE>(A1, A2, mBlock + ra,      kg, M);
        pa1 = fetchA<MODE>(A1, A2, mBlock + ra + 64, kg, M);
        pb0 = fetchB<MODE>(W, ra,       kg);
        pb1 = fetchB<MODE>(W, ra + 64,  kg);
        pb2 = fetchB<MODE>(W, ra + 128, kg);
        pb3 = fetchB<MODE>(W, ra + 192, kg);
        As[0][ka][ra]      = pa0;
        As[0][ka][ra + 64] = pa1;
        Bs[0][ka][ra]        = pb0;
        Bs[0][ka][ra + 64]   = pb1;
        Bs[0][ka][ra + 128]  = pb2;
        Bs[0][ka][ra + 192]  = pb3;
    }
    __syncthreads();

    constexpr int STEPS = KP / 8;
#pragma unroll 1
    for (int s = 0; s < STEPS; ++s) {
        const int cur = s & 1;
        if (s + 1 < STEPS) {
            const int kg = (s + 1) * 8 + ka;
            pa0 = fetchA<MODE>(A1, A2, mBlock + ra,      kg, M);
            pa1 = fetchA<MODE>(A1, A2, mBlock + ra + 64, kg, M);
            pb0 = fetchB<MODE>(W, ra,       kg);
            pb1 = fetchB<MODE>(W, ra + 64,  kg);
            pb2 = fetchB<MODE>(W, ra + 128, kg);
            pb3 = fetchB<MODE>(W, ra + 192, kg);
        }
#pragma unroll
        for (int k = 0; k < 8; ++k) {
            float a[8], b[8];
            *(float4*)&a[0] = *(const float4*)&As[cur][k][ty * 8];
            *(float4*)&a[4] = *(const float4*)&As[cur][k][ty * 8 + 4];
            *(float4*)&b[0] = *(const float4*)&Bs[cur][k][tx * 8];
            *(float4*)&b[4] = *(const float4*)&Bs[cur][k][tx * 8 + 4];
#pragma unroll
            for (int i = 0; i < 8; ++i)
#pragma unroll
                for (int j = 0; j < 8; ++j)
                    acc[i][j] = fmaf(a[i], b[j], acc[i][j]);
        }
        if (s + 1 < STEPS) {
            const int nxt = (s + 1) & 1;
            As[nxt][ka][ra]      = pa0;
            As[nxt][ka][ra + 64] = pa1;
            Bs[nxt][ka][ra]        = pb0;
            Bs[nxt][ka][ra + 64]   = pb1;
            Bs[nxt][ka][ra + 128]  = pb2;
            Bs[nxt][ka][ra + 192]  = pb3;
            __syncthreads();
        }
    }

    // --- epilogue ---
    const int n0 = tx * 8;
#pragma unroll
    for (int i = 0; i < 8; ++i) {
        const int m = mBlock + ty * 8 + i;
        if (m >= M) continue;
        const size_t off = (size_t)m * HIDDEN + n0;
        float v[8];
#pragma unroll
        for (int j = 0; j < 8; ++j) v[j] = acc[i][j];

        if (MODE == 1) {
            const float4 e0 = *(const float4*)&extra[off];
            const float4 e1 = *(const float4*)&extra[off + 4];
            v[0] += e0.x; v[1] += e0.y; v[2] += e0.z; v[3] += e0.w;
            v[4] += e1.x; v[5] += e1.y; v[6] += e1.z; v[7] += e1.w;
        }
        if (MODE == 2) {
#pragma unroll
            for (int j = 0; j < 8; ++j) v[j] += __ldg(&extra[n0 + j]);
        }
        if (MODE == 0) {
            float4 r0 = make_float4(v[0], v[1], v[2], v[3]);
            float4 r1 = make_float4(v[4], v[5], v[6], v[7]);
            *(float4*)&C2[off]     = r0;
            *(float4*)&C2[off + 4] = r1;
        }
#pragma unroll
        for (int j = 0; j < 8; ++j) v[j] = fmaxf(v[j], 0.0f);
        float4 r0 = make_float4(v[0], v[1], v[2], v[3]);
        float4 r1 = make_float4(v[4], v[5], v[6], v[7]);
        *(float4*)&C[off]     = r0;
        *(float4*)&C[off + 4] = r1;
    }
}

// ---------------------------------------------------------------------------
// Neighbor gather-sum: out[r,:] = sum_{j<6} msg[graph[r,j], :]
// One warp per row; each lane owns 8 floats (2 float4) -> each source row is
// read as one fully-coalesced 1KB burst per warp.
// ---------------------------------------------------------------------------
__global__ void gather_k(const float* __restrict__ msg, const int* __restrict__ graph,
                         float* __restrict__ outv, int nRows) {
    const int row = blockIdx.x * 8 + (threadIdx.x >> 5);
    if (row >= nRows) return;
    const int lane = threadIdx.x & 31;
    const int* g = graph + (size_t)row * MAX_NB;

    float4 s0 = make_float4(0.f, 0.f, 0.f, 0.f);
    float4 s1 = make_float4(0.f, 0.f, 0.f, 0.f);
#pragma unroll
    for (int j = 0; j < MAX_NB; ++j) {
        const float4* r = (const float4*)(msg + (size_t)g[j] * HIDDEN);
        const float4 v0 = __ldg(&r[lane]);
        const float4 v1 = __ldg(&r[lane + 32]);
        s0.x += v0.x; s0.y += v0.y; s0.z += v0.z; s0.w += v0.w;
        s1.x += v1.x; s1.y += v1.y; s1.z += v1.z; s1.w += v1.w;
    }
    float4* o = (float4*)(outv + (size_t)row * HIDDEN);
    o[lane]      = s0;
    o[lane + 32] = s1;
}

// ---------------------------------------------------------------------------
// Mean pool over 50 contiguous atoms per molecule.
// ---------------------------------------------------------------------------
__global__ void pool_k(const float* __restrict__ atomh, float* __restrict__ out) {
    const int mol = blockIdx.x;
    const int n   = threadIdx.x;
    const float* base = atomh + (size_t)mol * APM * HIDDEN;
    float s = 0.0f;
#pragma unroll
    for (int i = 0; i < APM; ++i) s += base[(size_t)i * HIDDEN + n];
    out[(size_t)mol * HIDDEN + n] = s * (1.0f / (float)APM);
}

// ---------------------------------------------------------------------------
extern "C" void kernel_launch(void* const* d_in, const int* in_sizes, int n_in,
                              void* d_out, int out_size) {
    const float* fatoms = (const float*)d_in[0];
    const float* fbonds = (const float*)d_in[1];
    const int*   agraph = (const int*)  d_in[2];
    const int*   bgraph = (const int*)  d_in[3];
    // d_in[4] = scope (structure is fixed: mol m owns atoms [m*50, m*50+50))
    const float* W_i = (const float*)d_in[5];
    const float* W_h = (const float*)d_in[6];
    const float* W_o = (const float*)d_in[7];
    const float* b_o = (const float*)d_in[8];
    float* out = (float*)d_out;

    float *binput, *msg0, *msg1, *nei, *anei, *atomh;
    cudaGetSymbolAddress((void**)&binput, g_binput);
    cudaGetSymbolAddress((void**)&msg0,   g_msg0);
    cudaGetSymbolAddress((void**)&msg1,   g_msg1);
    cudaGetSymbolAddress((void**)&nei,    g_nei);
    cudaGetSymbolAddress((void**)&anei,   g_anei);
    cudaGetSymbolAddress((void**)&atomh,  g_atomh);

    const dim3 blk(512);
    const dim3 gBonds(1, (N_BONDS + 127) / 128);
    const dim3 gAtoms(1, (N_ATOMS + 127) / 128);

    // init: binput = fbonds @ W_i^T ; msg0 = relu(binput)
    gemm_k<0, 56><<<gBonds, blk>>>(fbonds, nullptr, W_i, nullptr, msg0, binput, N_BONDS);

    // 5 message-passing rounds
    float* cur = msg0;
    float* nxt = msg1;
    for (int r = 0; r < 5; ++r) {
        gather_k<<<(N_BONDS + 7) / 8, 256>>>(cur, bgraph, nei, N_BONDS);
        gemm_k<1, 256><<<gBonds, blk>>>(nei, nullptr, W_h, binput, nxt, nullptr, N_BONDS);
        float* t = cur; cur = nxt; nxt = t;
    }

    // atom readout
    gather_k<<<(N_ATOMS + 7) / 8, 256>>>(cur, agraph, anei, N_ATOMS);
    gemm_k<2, 296><<<gAtoms, blk>>>(fatoms, anei, W_o, b_o, atomh, nullptr, N_ATOMS);

    // mean pool
    pool_k<<<N_MOLS, 256>>>(atomh, out);
}

// round 4
// speedup vs baseline: 2.1973x; 2.1973x over previous
#include <cuda_runtime.h>
#include <cstdint>
#include <cstddef>

// ---------------------------------------------------------------------------
// Problem constants
// ---------------------------------------------------------------------------
constexpr int N_ATOMS  = 100000;
constexpr int N_BONDS  = 200001;
constexpr int ATOM_FDIM = 39;
constexpr int IN_FDIM   = 50;
constexpr int OUT_FDIM  = 295;
constexpr int MAX_NB    = 6;
constexpr int HIDDEN    = 256;
constexpr int N_MOLS    = 2000;
constexpr int APM       = 50;

constexpr int KP0 = 64;    // init K (50 -> 64)
constexpr int KP1 = 256;   // rounds K
constexpr int KP2 = 320;   // readout K: [nei(256) | fatoms(39) | pad]

// ---------------------------------------------------------------------------
// Scratch
// ---------------------------------------------------------------------------
__device__ float g_binput[(size_t)N_BONDS * HIDDEN];
__device__ float g_msg0  [(size_t)N_BONDS * HIDDEN];
__device__ float g_msg1  [(size_t)N_BONDS * HIDDEN];
__device__ float g_nei   [(size_t)N_BONDS * HIDDEN];
__device__ float g_atomh [(size_t)N_ATOMS * HIDDEN];
__device__ float g_fbpad [(size_t)N_BONDS * KP0];
__device__ float g_acat  [(size_t)N_ATOMS * KP2];
__device__ float g_Wit   [(size_t)KP0 * HIDDEN];   // transposed [K][256], tf32-rounded
__device__ float g_Wht   [(size_t)KP1 * HIDDEN];
__device__ float g_Wot   [(size_t)KP2 * HIDDEN];

// ---------------------------------------------------------------------------
// Helpers
// ---------------------------------------------------------------------------
__device__ __forceinline__ uint32_t smem_u32(const void* p) {
    uint32_t a;
    asm("{ .reg .u64 t; cvta.to.shared.u64 t, %1; cvt.u32.u64 %0, t; }" : "=r"(a) : "l"(p));
    return a;
}
__device__ __forceinline__ float to_tf32(float x) {
    uint32_t u;
    asm("cvt.rna.tf32.f32 %0, %1;" : "=r"(u) : "f"(x));
    return __uint_as_float(u);
}
__device__ __forceinline__ void cp16(uint32_t dst, const void* src, uint32_t sz) {
    asm volatile("cp.async.ca.shared.global [%0], [%1], 16, %2;" :: "r"(dst), "l"(src), "r"(sz) : "memory");
}
__device__ __forceinline__ void cp_commit() {
    asm volatile("cp.async.commit_group;" ::: "memory");
}
template <int N>
__device__ __forceinline__ void cp_wait() {
    asm volatile("cp.async.wait_group %0;" :: "n"(N) : "memory");
}
__device__ __forceinline__ void mma8(float& d0, float& d1, float& d2, float& d3,
                                     uint32_t a0, uint32_t a1, uint32_t a2, uint32_t a3,
                                     uint32_t b0, uint32_t b1) {
    asm volatile(
        "mma.sync.aligned.m16n8k8.row.col.f32.tf32.tf32.f32 "
        "{%0,%1,%2,%3}, {%4,%5,%6,%7}, {%8,%9}, {%0,%1,%2,%3};"
        : "+f"(d0), "+f"(d1), "+f"(d2), "+f"(d3)
        : "r"(a0), "r"(a1), "r"(a2), "r"(a3), "r"(b0), "r"(b1));
}

// SMEM layout (floats): As[2] @ buf*4096 (128x32, xor-swizzled float4),
// Bs[2] @ 8192 + buf*8448 (32 x 264 padded rows). Total 25088 floats = 100352 B.
constexpr int AS_F = 4096;
constexpr int BS_F = 8448;   // 32*264
constexpr int BS_BASE = 8192;
constexpr int SMEM_BYTES = (BS_BASE + 2 * BS_F) * 4;

// ---------------------------------------------------------------------------
// tf32 mma.sync GEMM: C[M,256] = epi( A[M,K] @ Bt[K,256] )
// Bt is pre-transposed, tf32-rounded. A is tf32-rounded.
// MODE 0: C2 <- raw, C <- relu(raw)     (init)
// MODE 1: C <- relu(extra[m,:] + raw)   (rounds, extra = binput)
// MODE 2: C <- relu(raw + extra[n])     (readout, extra = b_o)
// ---------------------------------------------------------------------------
template <int MODE, int KT>
__global__ void __launch_bounds__(512, 1)
gemm_mma(const float4* __restrict__ A, int lda4,
         const float4* __restrict__ Bt,
         const float* __restrict__ extra,
         float* __restrict__ C, float* __restrict__ C2, int M) {
    extern __shared__ float sm[];
    const uint32_t sbase = smem_u32(sm);
    const int tid  = threadIdx.x;
    const int wid  = tid >> 5;
    const int lane = tid & 31;
    const int mBase = blockIdx.x * 128;
    const int warpM = (wid >> 3) * 64;     // 0 or 64
    const int warpN = (wid & 7) * 32;      // 0..224

    // --- staging lambdas ---
    auto stageA = [&](int s, int buf) {
#pragma unroll
        for (int i = 0; i < 2; ++i) {
            int e = tid + i * 512;
            int m = e >> 3, c4 = e & 7;
            int gm = mBase + m;
            const float4* src = A + (size_t)gm * lda4 + s * 8 + c4;
            uint32_t dst = sbase + (uint32_t)(buf * AS_F + m * 32 + (((c4) ^ (m & 7)) << 2)) * 4u;
            cp16(dst, src, (gm < M) ? 16u : 0u);
        }
    };
    auto stageB = [&](int s, int buf) {
#pragma unroll
        for (int i = 0; i < 4; ++i) {
            int e = tid + i * 512;
            int k = e >> 6, n4 = e & 63;
            const float4* src = Bt + (size_t)(s * 32 + k) * 64 + n4;
            uint32_t dst = sbase + (uint32_t)(BS_BASE + buf * BS_F + k * 264 + n4 * 4) * 4u;
            cp16(dst, src, 16u);
        }
    };

    stageA(0, 0); stageB(0, 0); cp_commit();
    if (KT > 1) { stageA(1, 1); stageB(1, 1); cp_commit(); }

    float acc[4][4][4];
#pragma unroll
    for (int a = 0; a < 4; ++a)
#pragma unroll
        for (int b = 0; b < 4; ++b)
#pragma unroll
            for (int c = 0; c < 4; ++c) acc[a][b][c] = 0.0f;

#pragma unroll 1
    for (int s = 0; s < KT; ++s) {
        if (s + 1 < KT) cp_wait<1>(); else cp_wait<0>();
        __syncthreads();
        const float* bA = sm + (s & 1) * AS_F;
        const float* bB = sm + BS_BASE + (s & 1) * BS_F;

#pragma unroll
        for (int ks = 0; ks < 4; ++ks) {
            uint32_t afr[4][4];
            const int c0 = ks * 8 + (lane & 3);
            const int c1 = c0 + 4;
#pragma unroll
            for (int mt = 0; mt < 4; ++mt) {
                const int r0 = warpM + mt * 16 + (lane >> 2);
                const int r1 = r0 + 8;
                afr[mt][0] = __float_as_uint(bA[r0 * 32 + (((c0 >> 2) ^ (r0 & 7)) << 2) + (c0 & 3)]);
                afr[mt][1] = __float_as_uint(bA[r1 * 32 + (((c0 >> 2) ^ (r1 & 7)) << 2) + (c0 & 3)]);
                afr[mt][2] = __float_as_uint(bA[r0 * 32 + (((c1 >> 2) ^ (r0 & 7)) << 2) + (c1 & 3)]);
                afr[mt][3] = __float_as_uint(bA[r1 * 32 + (((c1 >> 2) ^ (r1 & 7)) << 2) + (c1 & 3)]);
            }
            const int k0 = ks * 8 + (lane & 3);
#pragma unroll
            for (int nt = 0; nt < 4; ++nt) {
                const int nn = warpN + nt * 8 + (lane >> 2);
                uint32_t b0 = __float_as_uint(bB[k0 * 264 + nn]);
                uint32_t b1 = __float_as_uint(bB[(k0 + 4) * 264 + nn]);
#pragma unroll
                for (int mt = 0; mt < 4; ++mt)
                    mma8(acc[mt][nt][0], acc[mt][nt][1], acc[mt][nt][2], acc[mt][nt][3],
                         afr[mt][0], afr[mt][1], afr[mt][2], afr[mt][3], b0, b1);
            }
        }
        __syncthreads();
        if (s + 2 < KT) { stageA(s + 2, s & 1); stageB(s + 2, s & 1); cp_commit(); }
    }

    // --- epilogue ---
#pragma unroll
    for (int mt = 0; mt < 4; ++mt) {
#pragma unroll
        for (int rg = 0; rg < 2; ++rg) {
            const int r = mBase + warpM + mt * 16 + (lane >> 2) + rg * 8;
            if (r < M) {
#pragma unroll
                for (int nt = 0; nt < 4; ++nt) {
                    const int col = warpN + nt * 8 + (lane & 3) * 2;
                    const size_t off = (size_t)r * HIDDEN + col;
                    float v0 = acc[mt][nt][rg * 2 + 0];
                    float v1 = acc[mt][nt][rg * 2 + 1];
                    if (MODE == 1) {
                        float2 e = *(const float2*)(extra + off);
                        v0 += e.x; v1 += e.y;
                    }
                    if (MODE == 2) {
                        v0 += __ldg(extra + col);
                        v1 += __ldg(extra + col + 1);
                    }
                    if (MODE == 0) *(float2*)(C2 + off) = make_float2(v0, v1);
                    v0 = fmaxf(v0, 0.0f); v1 = fmaxf(v1, 0.0f);
                    *(float2*)(C + off) = make_float2(v0, v1);
                }
            }
        }
    }
}

// ---------------------------------------------------------------------------
// Producers: all GEMM operands are tf32-rounded here (rna), so mma inputs are
// exact tf32; activations/residuals elsewhere stay full fp32.
// ---------------------------------------------------------------------------
__global__ void pad_fb_k(const float* __restrict__ in, float* __restrict__ out) {
    size_t i = (size_t)blockIdx.x * blockDim.x + threadIdx.x;
    if (i >= (size_t)N_BONDS * KP0) return;
    int r = (int)(i / KP0), c = (int)(i % KP0);
    out[i] = (c < IN_FDIM) ? to_tf32(in[(size_t)r * IN_FDIM + c]) : 0.0f;
}
__global__ void tr_wi_k(const float* __restrict__ W, float* __restrict__ out) {
    int i = blockIdx.x * blockDim.x + threadIdx.x;
    if (i >= KP0 * HIDDEN) return;
    int k = i / HIDDEN, n = i % HIDDEN;
    out[i] = (k < IN_FDIM) ? to_tf32(W[(size_t)n * IN_FDIM + k]) : 0.0f;
}
__global__ void tr_wh_k(const float* __restrict__ W, float* __restrict__ out) {
    int i = blockIdx.x * blockDim.x + threadIdx.x;
    if (i >= KP1 * HIDDEN) return;
    int k = i / HIDDEN, n = i % HIDDEN;
    out[i] = to_tf32(W[(size_t)n * HIDDEN + k]);
}
// Wo columns reordered to match acat: [hidden(256) | atom(39) | pad]
__global__ void tr_wo_k(const float* __restrict__ W, float* __restrict__ out) {
    int i = blockIdx.x * blockDim.x + threadIdx.x;
    if (i >= KP2 * HIDDEN) return;
    int k = i / HIDDEN, n = i % HIDDEN;
    float v = 0.0f;
    if (k < 256) v = to_tf32(W[(size_t)n * OUT_FDIM + ATOM_FDIM + k]);
    else if (k < OUT_FDIM) v = to_tf32(W[(size_t)n * OUT_FDIM + (k - 256)]);
    out[i] = v;
}
__global__ void pad_acat_k(const float* __restrict__ fatoms, float* __restrict__ acat) {
    int i = blockIdx.x * blockDim.x + threadIdx.x;
    if (i >= N_ATOMS * 64) return;
    int r = i / 64, c = 256 + (i % 64);
    acat[(size_t)r * KP2 + c] =
        (c < OUT_FDIM) ? to_tf32(fatoms[(size_t)r * ATOM_FDIM + (c - 256)]) : 0.0f;
}

// ---------------------------------------------------------------------------
// Gather-sum (warp per row), tf32-rounded output (it is only a GEMM input).
// ---------------------------------------------------------------------------
__global__ void gather_k(const float* __restrict__ msg, const int* __restrict__ graph,
                         float4* __restrict__ outv, int ldo4, int nRows) {
    const int row = blockIdx.x * 8 + (threadIdx.x >> 5);
    if (row >= nRows) return;
    const int lane = threadIdx.x & 31;
    const int* g = graph + (size_t)row * MAX_NB;

    float4 s0 = make_float4(0.f, 0.f, 0.f, 0.f);
    float4 s1 = make_float4(0.f, 0.f, 0.f, 0.f);
#pragma unroll
    for (int j = 0; j < MAX_NB; ++j) {
        const float4* r = (const float4*)(msg + (size_t)g[j] * HIDDEN);
        const float4 v0 = __ldg(&r[lane]);
        const float4 v1 = __ldg(&r[lane + 32]);
        s0.x += v0.x; s0.y += v0.y; s0.z += v0.z; s0.w += v0.w;
        s1.x += v1.x; s1.y += v1.y; s1.z += v1.z; s1.w += v1.w;
    }
    s0 = make_float4(to_tf32(s0.x), to_tf32(s0.y), to_tf32(s0.z), to_tf32(s0.w));
    s1 = make_float4(to_tf32(s1.x), to_tf32(s1.y), to_tf32(s1.z), to_tf32(s1.w));
    float4* o = outv + (size_t)row * ldo4;
    o[lane]      = s0;
    o[lane + 32] = s1;
}

__global__ void pool_k(const float* __restrict__ atomh, float* __restrict__ out) {
    const int mol = blockIdx.x;
    const int n   = threadIdx.x;
    const float* base = atomh + (size_t)mol * APM * HIDDEN;
    float s = 0.0f;
#pragma unroll
    for (int i = 0; i < APM; ++i) s += base[(size_t)i * HIDDEN + n];
    out[(size_t)mol * HIDDEN + n] = s * (1.0f / (float)APM);
}

// ---------------------------------------------------------------------------
extern "C" void kernel_launch(void* const* d_in, const int* in_sizes, int n_in,
                              void* d_out, int out_size) {
    const float* fatoms = (const float*)d_in[0];
    const float* fbonds = (const float*)d_in[1];
    const int*   agraph = (const int*)  d_in[2];
    const int*   bgraph = (const int*)  d_in[3];
    const float* W_i = (const float*)d_in[5];
    const float* W_h = (const float*)d_in[6];
    const float* W_o = (const float*)d_in[7];
    const float* b_o = (const float*)d_in[8];
    float* out = (float*)d_out;

    float *binput, *msg0, *msg1, *nei, *atomh, *fbpad, *acat, *Wit, *Wht, *Wot;
    cudaGetSymbolAddress((void**)&binput, g_binput);
    cudaGetSymbolAddress((void**)&msg0,   g_msg0);
    cudaGetSymbolAddress((void**)&msg1,   g_msg1);
    cudaGetSymbolAddress((void**)&nei,    g_nei);
    cudaGetSymbolAddress((void**)&atomh,  g_atomh);
    cudaGetSymbolAddress((void**)&fbpad,  g_fbpad);
    cudaGetSymbolAddress((void**)&acat,   g_acat);
    cudaGetSymbolAddress((void**)&Wit,    g_Wit);
    cudaGetSymbolAddress((void**)&Wht,    g_Wht);
    cudaGetSymbolAddress((void**)&Wot,    g_Wot);

    cudaFuncSetAttribute(gemm_mma<0, KP0 / 32>, cudaFuncAttributeMaxDynamicSharedMemorySize, SMEM_BYTES);
    cudaFuncSetAttribute(gemm_mma<1, KP1 / 32>, cudaFuncAttributeMaxDynamicSharedMemorySize, SMEM_BYTES);
    cudaFuncSetAttribute(gemm_mma<2, KP2 / 32>, cudaFuncAttributeMaxDynamicSharedMemorySize, SMEM_BYTES);

    // producers
    {
        size_t n = (size_t)N_BONDS * KP0;
        pad_fb_k<<<(unsigned)((n + 255) / 256), 256>>>(fbonds, fbpad);
        tr_wi_k<<<(KP0 * HIDDEN + 255) / 256, 256>>>(W_i, Wit);
        tr_wh_k<<<(KP1 * HIDDEN + 255) / 256, 256>>>(W_h, Wht);
        tr_wo_k<<<(KP2 * HIDDEN + 255) / 256, 256>>>(W_o, Wot);
        pad_acat_k<<<(N_ATOMS * 64 + 255) / 256, 256>>>(fatoms, acat);
    }

    const int tilesB = (N_BONDS + 127) / 128;
    const int tilesA = (N_ATOMS + 127) / 128;

    // init GEMM: binput(raw) + msg0 = relu
    gemm_mma<0, KP0 / 32><<<tilesB, 512, SMEM_BYTES>>>(
        (const float4*)fbpad, KP0 / 4, (const float4*)Wit, nullptr, msg0, binput, N_BONDS);

    // 5 message-passing rounds
    float* cur = msg0;
    float* nxt = msg1;
    for (int r = 0; r < 5; ++r) {
        gather_k<<<(N_BONDS + 7) / 8, 256>>>(cur, bgraph, (float4*)nei, HIDDEN / 4, N_BONDS);
        gemm_mma<1, KP1 / 32><<<tilesB, 512, SMEM_BYTES>>>(
            (const float4*)nei, KP1 / 4, (const float4*)Wht, binput, nxt, nullptr, N_BONDS);
        float* t = cur; cur = nxt; nxt = t;
    }

    // atom readout
    gather_k<<<(N_ATOMS + 7) / 8, 256>>>(cur, agraph, (float4*)acat, KP2 / 4, N_ATOMS);
    gemm_mma<2, KP2 / 32><<<tilesA, 512, SMEM_BYTES>>>(
        (const float4*)acat, KP2 / 4, (const float4*)Wot, b_o, atomh, nullptr, N_ATOMS);

    // mean pool
    pool_k<<<N_MOLS, 256>>>(atomh, out);
}

// round 6
// speedup vs baseline: 2.3576x; 1.0730x over previous
#include <cuda_runtime.h>
#include <cstdint>
#include <cstddef>

// ---------------------------------------------------------------------------
// Problem constants
// ---------------------------------------------------------------------------
constexpr int N_ATOMS  = 100000;
constexpr int N_BONDS  = 200001;
constexpr int ATOM_FDIM = 39;
constexpr int IN_FDIM   = 50;
constexpr int OUT_FDIM  = 295;
constexpr int MAX_NB    = 6;
constexpr int HIDDEN    = 256;
constexpr int N_MOLS    = 2000;
constexpr int APM       = 50;

constexpr int KP0 = 64;    // init K (50 -> 64)
constexpr int KP1 = 256;   // rounds K
constexpr int KP2 = 320;   // readout K: [nei(256) | fatoms(39) | pad]
constexpr int BK  = 16;

// ---------------------------------------------------------------------------
// Scratch
// ---------------------------------------------------------------------------
__device__ float g_binput[(size_t)N_BONDS * HIDDEN];
__device__ float g_msg0  [(size_t)N_BONDS * HIDDEN];
__device__ float g_msg1  [(size_t)N_BONDS * HIDDEN];
__device__ float g_atomh [(size_t)N_ATOMS * HIDDEN];
__device__ float g_fbpad [(size_t)N_BONDS * KP0];
__device__ float g_afeat [(size_t)N_ATOMS * 64];   // tf32 fatoms, padded to 64
__device__ float g_Wit   [(size_t)KP0 * HIDDEN];   // transposed [K][256], tf32
__device__ float g_Wht   [(size_t)KP1 * HIDDEN];
__device__ float g_Wot   [(size_t)KP2 * HIDDEN];

// ---------------------------------------------------------------------------
// Helpers
// ---------------------------------------------------------------------------
__device__ __forceinline__ uint32_t smem_u32(const void* p) {
    uint32_t a;
    asm("{ .reg .u64 t; cvta.to.shared.u64 t, %1; cvt.u32.u64 %0, t; }" : "=r"(a) : "l"(p));
    return a;
}
__device__ __forceinline__ float to_tf32(float x) {
    uint32_t u;
    asm("cvt.rna.tf32.f32 %0, %1;" : "=r"(u) : "f"(x));
    return __uint_as_float(u);
}
__device__ __forceinline__ void cp16(uint32_t dst, const void* src, uint32_t sz) {
    asm volatile("cp.async.ca.shared.global [%0], [%1], 16, %2;" :: "r"(dst), "l"(src), "r"(sz) : "memory");
}
__device__ __forceinline__ void cp_commit() {
    asm volatile("cp.async.commit_group;" ::: "memory");
}
template <int N>
__device__ __forceinline__ void cp_wait() {
    asm volatile("cp.async.wait_group %0;" :: "n"(N) : "memory");
}
__device__ __forceinline__ void mma8(float& d0, float& d1, float& d2, float& d3,
                                     uint32_t a0, uint32_t a1, uint32_t a2, uint32_t a3,
                                     uint32_t b0, uint32_t b1) {
    asm volatile(
        "mma.sync.aligned.m16n8k8.row.col.f32.tf32.tf32.f32 "
        "{%0,%1,%2,%3}, {%4,%5,%6,%7}, {%8,%9}, {%0,%1,%2,%3};"
        : "+f"(d0), "+f"(d1), "+f"(d2), "+f"(d3)
        : "r"(a0), "r"(a1), "r"(a2), "r"(a3), "r"(b0), "r"(b1));
}

// SMEM layout (floats), THREE-stage buffers — cp.async(s+2) targets buf (s+2)%3,
// never the buffer the current iteration's mma is reading (fixes R5's WAR race).
//   [0,768)        gidx (int) — 128 rows x 6 neighbor indices
//   [768, +3*2560) A bufs: 128 rows x stride 20
//   [8448, +3*4224) B bufs: 16 rows x stride 264
constexpr int GOFF   = 0;
constexpr int AOFF   = 768;
constexpr int A_BUF  = 128 * 20;            // 2560
constexpr int BOFF   = AOFF + 3 * A_BUF;    // 8448
constexpr int B_BUF  = BK * 264;            // 4224
constexpr int SMEM_F = BOFF + 3 * B_BUF;    // 21120 floats
constexpr int SMEM_BYTES = SMEM_F * 4;      // 84480 B

// ---------------------------------------------------------------------------
// Fused gather + tf32 mma.sync GEMM.
// MODE 0: C2 <- raw, C <- relu(raw)     (init; no gather)
// MODE 1: C <- relu(extra[m,:] + raw)   (rounds; all chunks gathered)
// MODE 2: C <- relu(raw + extra[n])     (readout; chunks <16 gathered)
// ---------------------------------------------------------------------------
template <int MODE, int KT>
__global__ void __launch_bounds__(512, 1)
gemm_fused(const float* __restrict__ msg,
           const int* __restrict__ graph,
           const float4* __restrict__ Apad, int lda4,
           const float4* __restrict__ Bt,
           const float* __restrict__ extra,
           float* __restrict__ C, float* __restrict__ C2, int M) {
    extern __shared__ float sm[];
    int* sgidx = (int*)(sm + GOFF);
    const uint32_t sbase = smem_u32(sm);
    const int tid  = threadIdx.x;
    const int wid  = tid >> 5;
    const int lane = tid & 31;
    const int mBase = blockIdx.x * 128;
    const int warpM = (wid >> 3) * 64;
    const int warpN = (wid & 7) * 32;

    constexpr int FEAT0 = (MODE == 2) ? 16 : 0;
    auto gathered = [](int s) { return MODE == 1 || (MODE == 2 && s < 16); };

    const int grow = tid >> 2;       // 0..127
    const int gc4  = tid & 3;        // float4 within 16-col chunk

    if (MODE != 0) {
#pragma unroll
        for (int i = tid; i < 128 * MAX_NB; i += 512) {
            int gi = mBase * MAX_NB + i;
            sgidx[i] = (gi < M * MAX_NB) ? graph[gi] : 0;
        }
        __syncthreads();
    }

    float4 v[6];   // held gather prefetch for the next chunk

    auto issue_gather = [&](int s) {
#pragma unroll
        for (int j = 0; j < 6; ++j) {
            int idx = sgidx[grow * 6 + j];
            v[j] = __ldg((const float4*)(msg + (size_t)idx * HIDDEN + s * BK) + gc4);
        }
    };
    auto store_gather = [&](int s) {
        float4 a;
        a.x = v[0].x + v[1].x + v[2].x + v[3].x + v[4].x + v[5].x;
        a.y = v[0].y + v[1].y + v[2].y + v[3].y + v[4].y + v[5].y;
        a.z = v[0].z + v[1].z + v[2].z + v[3].z + v[4].z + v[5].z;
        a.w = v[0].w + v[1].w + v[2].w + v[3].w + v[4].w + v[5].w;
        a = make_float4(to_tf32(a.x), to_tf32(a.y), to_tf32(a.z), to_tf32(a.w));
        *(float4*)(sm + AOFF + (s % 3) * A_BUF + grow * 20 + gc4 * 4) = a;
    };
    auto cpA = [&](int s) {
        int gm = mBase + grow;
        const float4* src = Apad + (size_t)gm * lda4 + (s - FEAT0) * 4 + gc4;
        uint32_t dst = sbase + (uint32_t)(AOFF + (s % 3) * A_BUF + grow * 20 + gc4 * 4) * 4u;
        cp16(dst, src, (gm < M) ? 16u : 0u);
    };
    auto cpB = [&](int s) {
#pragma unroll
        for (int i = 0; i < 2; ++i) {
            int e = tid + i * 512;
            int k = e >> 6, n4 = e & 63;
            const float4* src = Bt + (size_t)(s * BK + k) * 64 + n4;
            uint32_t dst = sbase + (uint32_t)(BOFF + (s % 3) * B_BUF + k * 264 + n4 * 4) * 4u;
            cp16(dst, src, 16u);
        }
    };

    // --- prologue: chunks 0 and 1 ---
    if (gathered(0)) { issue_gather(0); store_gather(0); }
    else cpA(0);
    cpB(0); cp_commit();
    if (KT > 1) {
        if (gathered(1)) issue_gather(1);   // hold in regs; stored during s=0
        else cpA(1);
        cpB(1); cp_commit();
    }
    cp_wait<1>();
    __syncthreads();

    float acc[4][4][4];
#pragma unroll
    for (int a = 0; a < 4; ++a)
#pragma unroll
        for (int b = 0; b < 4; ++b)
#pragma unroll
            for (int c = 0; c < 4; ++c) acc[a][b][c] = 0.0f;

#pragma unroll 1
    for (int s = 0; s < KT; ++s) {
        const float* bA = sm + AOFF + (s % 3) * A_BUF;
        const float* bB = sm + BOFF + (s % 3) * B_BUF;

#pragma unroll
        for (int ks = 0; ks < 2; ++ks) {
            uint32_t afr[4][4];
            const int c0 = ks * 8 + (lane & 3);
            const int c1 = c0 + 4;
#pragma unroll
            for (int mt = 0; mt < 4; ++mt) {
                const int r0 = warpM + mt * 16 + (lane >> 2);
                const int r1 = r0 + 8;
                afr[mt][0] = __float_as_uint(bA[r0 * 20 + c0]);
                afr[mt][1] = __float_as_uint(bA[r1 * 20 + c0]);
                afr[mt][2] = __float_as_uint(bA[r0 * 20 + c1]);
                afr[mt][3] = __float_as_uint(bA[r1 * 20 + c1]);
            }
#pragma unroll
            for (int nt = 0; nt < 4; ++nt) {
                const int nn = warpN + nt * 8 + (lane >> 2);
                uint32_t b0 = __float_as_uint(bB[c0 * 264 + nn]);
                uint32_t b1 = __float_as_uint(bB[c1 * 264 + nn]);
#pragma unroll
                for (int mt = 0; mt < 4; ++mt)
                    mma8(acc[mt][nt][0], acc[mt][nt][1], acc[mt][nt][2], acc[mt][nt][3],
                         afr[mt][0], afr[mt][1], afr[mt][2], afr[mt][3], b0, b1);
            }
        }

        // stage next: writes go to buf (s+1)%3 and (s+2)%3 — never buf s%3
        if (s + 1 < KT && gathered(s + 1)) store_gather(s + 1);
        if (s + 2 < KT) {
            if (gathered(s + 2)) issue_gather(s + 2);
            else cpA(s + 2);
            cpB(s + 2);
        }
        cp_commit();
        cp_wait<1>();
        __syncthreads();
    }

    // --- epilogue ---
#pragma unroll
    for (int mt = 0; mt < 4; ++mt) {
#pragma unroll
        for (int rg = 0; rg < 2; ++rg) {
            const int r = mBase + warpM + mt * 16 + (lane >> 2) + rg * 8;
            if (r < M) {
#pragma unroll
                for (int nt = 0; nt < 4; ++nt) {
                    const int col = warpN + nt * 8 + (lane & 3) * 2;
                    const size_t off = (size_t)r * HIDDEN + col;
                    float v0 = acc[mt][nt][rg * 2 + 0];
                    float v1 = acc[mt][nt][rg * 2 + 1];
                    if (MODE == 1) {
                        float2 e = *(const float2*)(extra + off);
                        v0 += e.x; v1 += e.y;
                    }
                    if (MODE == 2) {
                        v0 += __ldg(extra + col);
                        v1 += __ldg(extra + col + 1);
                    }
                    if (MODE == 0) *(float2*)(C2 + off) = make_float2(v0, v1);
                    v0 = fmaxf(v0, 0.0f); v1 = fmaxf(v1, 0.0f);
                    *(float2*)(C + off) = make_float2(v0, v1);
                }
            }
        }
    }
}

// ---------------------------------------------------------------------------
// Producers (tf32 pre-rounding of all pure GEMM operands)
// ---------------------------------------------------------------------------
__global__ void pad_fb_k(const float* __restrict__ in, float* __restrict__ out) {
    size_t i = (size_t)blockIdx.x * blockDim.x + threadIdx.x;
    if (i >= (size_t)N_BONDS * KP0) return;
    int r = (int)(i / KP0), c = (int)(i % KP0);
    out[i] = (c < IN_FDIM) ? to_tf32(in[(size_t)r * IN_FDIM + c]) : 0.0f;
}
__global__ void tr_wi_k(const float* __restrict__ W, float* __restrict__ out) {
    int i = blockIdx.x * blockDim.x + threadIdx.x;
    if (i >= KP0 * HIDDEN) return;
    int k = i / HIDDEN, n = i % HIDDEN;
    out[i] = (k < IN_FDIM) ? to_tf32(W[(size_t)n * IN_FDIM + k]) : 0.0f;
}
__global__ void tr_wh_k(const float* __restrict__ W, float* __restrict__ out) {
    int i = blockIdx.x * blockDim.x + threadIdx.x;
    if (i >= KP1 * HIDDEN) return;
    int k = i / HIDDEN, n = i % HIDDEN;
    out[i] = to_tf32(W[(size_t)n * HIDDEN + k]);
}
__global__ void tr_wo_k(const float* __restrict__ W, float* __restrict__ out) {
    int i = blockIdx.x * blockDim.x + threadIdx.x;
    if (i >= KP2 * HIDDEN) return;
    int k = i / HIDDEN, n = i % HIDDEN;
    float v = 0.0f;
    if (k < 256) v = to_tf32(W[(size_t)n * OUT_FDIM + ATOM_FDIM + k]);
    else if (k < OUT_FDIM) v = to_tf32(W[(size_t)n * OUT_FDIM + (k - 256)]);
    out[i] = v;
}
__global__ void pad_afeat_k(const float* __restrict__ fatoms, float* __restrict__ afeat) {
    int i = blockIdx.x * blockDim.x + threadIdx.x;
    if (i >= N_ATOMS * 64) return;
    int r = i / 64, c = i % 64;
    afeat[i] = (c < ATOM_FDIM) ? to_tf32(fatoms[(size_t)r * ATOM_FDIM + c]) : 0.0f;
}

__global__ void pool_k(const float* __restrict__ atomh, float* __restrict__ out) {
    const int mol = blockIdx.x;
    const int n   = threadIdx.x;
    const float* base = atomh + (size_t)mol * APM * HIDDEN;
    float s = 0.0f;
#pragma unroll
    for (int i = 0; i < APM; ++i) s += base[(size_t)i * HIDDEN + n];
    out[(size_t)mol * HIDDEN + n] = s * (1.0f / (float)APM);
}

// ---------------------------------------------------------------------------
extern "C" void kernel_launch(void* const* d_in, const int* in_sizes, int n_in,
                              void* d_out, int out_size) {
    const float* fatoms = (const float*)d_in[0];
    const float* fbonds = (const float*)d_in[1];
    const int*   agraph = (const int*)  d_in[2];
    const int*   bgraph = (const int*)  d_in[3];
    const float* W_i = (const float*)d_in[5];
    const float* W_h = (const float*)d_in[6];
    const float* W_o = (const float*)d_in[7];
    const float* b_o = (const float*)d_in[8];
    float* out = (float*)d_out;

    float *binput, *msg0, *msg1, *atomh, *fbpad, *afeat, *Wit, *Wht, *Wot;
    cudaGetSymbolAddress((void**)&binput, g_binput);
    cudaGetSymbolAddress((void**)&msg0,   g_msg0);
    cudaGetSymbolAddress((void**)&msg1,   g_msg1);
    cudaGetSymbolAddress((void**)&atomh,  g_atomh);
    cudaGetSymbolAddress((void**)&fbpad,  g_fbpad);
    cudaGetSymbolAddress((void**)&afeat,  g_afeat);
    cudaGetSymbolAddress((void**)&Wit,    g_Wit);
    cudaGetSymbolAddress((void**)&Wht,    g_Wht);
    cudaGetSymbolAddress((void**)&Wot,    g_Wot);

    cudaFuncSetAttribute(gemm_fused<0, KP0 / BK>, cudaFuncAttributeMaxDynamicSharedMemorySize, SMEM_BYTES);
    cudaFuncSetAttribute(gemm_fused<1, KP1 / BK>, cudaFuncAttributeMaxDynamicSharedMemorySize, SMEM_BYTES);
    cudaFuncSetAttribute(gemm_fused<2, KP2 / BK>, cudaFuncAttributeMaxDynamicSharedMemorySize, SMEM_BYTES);

    // producers
    {
        size_t n = (size_t)N_BONDS * KP0;
        pad_fb_k<<<(unsigned)((n + 255) / 256), 256>>>(fbonds, fbpad);
        tr_wi_k<<<(KP0 * HIDDEN + 255) / 256, 256>>>(W_i, Wit);
        tr_wh_k<<<(KP1 * HIDDEN + 255) / 256, 256>>>(W_h, Wht);
        tr_wo_k<<<(KP2 * HIDDEN + 255) / 256, 256>>>(W_o, Wot);
        pad_afeat_k<<<(N_ATOMS * 64 + 255) / 256, 256>>>(fatoms, afeat);
    }

    const int tilesB = (N_BONDS + 127) / 128;
    const int tilesA = (N_ATOMS + 127) / 128;

    // init GEMM: binput(raw) + msg0 = relu (A = fbpad via cp.async)
    gemm_fused<0, KP0 / BK><<<tilesB, 512, SMEM_BYTES>>>(
        nullptr, nullptr, (const float4*)fbpad, KP0 / 4,
        (const float4*)Wit, nullptr, msg0, binput, N_BONDS);

    // 5 message-passing rounds: gather fused into GEMM A-staging
    float* cur = msg0;
    float* nxt = msg1;
    for (int r = 0; r < 5; ++r) {
        gemm_fused<1, KP1 / BK><<<tilesB, 512, SMEM_BYTES>>>(
            cur, bgraph, nullptr, 0,
            (const float4*)Wht, binput, nxt, nullptr, N_BONDS);
        float* t = cur; cur = nxt; nxt = t;
    }

    // atom readout: fused atom gather (chunks 0-15) + afeat (chunks 16-19)
    gemm_fused<2, KP2 / BK><<<tilesA, 512, SMEM_BYTES>>>(
        cur, agraph, (const float4*)afeat, 16,
        (const float4*)Wot, b_o, atomh, nullptr, N_ATOMS);

    // mean pool
    pool_k<<<N_MOLS, 256>>>(atomh, out);
}

// round 7
// speedup vs baseline: 2.7917x; 1.1842x over previous
#include <cuda_runtime.h>
#include <cuda_fp16.h>
#include <cstdint>
#include <cstddef>

// ---------------------------------------------------------------------------
// Problem constants
// ---------------------------------------------------------------------------
constexpr int N_ATOMS  = 100000;
constexpr int N_BONDS  = 200001;
constexpr int ATOM_FDIM = 39;
constexpr int IN_FDIM   = 50;
constexpr int OUT_FDIM  = 295;
constexpr int MAX_NB    = 6;
constexpr int HIDDEN    = 256;
constexpr int N_MOLS    = 2000;
constexpr int APM       = 50;

constexpr int KP0 = 64;    // init K (50 -> 64)
constexpr int KP1 = 256;   // rounds K
constexpr int KP2 = 320;   // readout K: [nei(256) | fatoms(39) | pad]
constexpr int BK  = 16;    // one m16n8k16 step per chunk

// ---------------------------------------------------------------------------
// Scratch (fp16 activations/weights; fp32 only for atomh -> pool -> out)
// ---------------------------------------------------------------------------
__device__ __align__(16) __half g_binput[(size_t)N_BONDS * HIDDEN];
__device__ __align__(16) __half g_msg0  [(size_t)N_BONDS * HIDDEN];
__device__ __align__(16) __half g_msg1  [(size_t)N_BONDS * HIDDEN];
__device__ __align__(16) float  g_atomh [(size_t)N_ATOMS * HIDDEN];
__device__ __align__(16) __half g_fbpad [(size_t)N_BONDS * KP0];
__device__ __align__(16) __half g_afeat [(size_t)N_ATOMS * 64];
__device__ __align__(16) __half g_Wi    [(size_t)HIDDEN * KP0];   // [n][k]
__device__ __align__(16) __half g_Wh    [(size_t)HIDDEN * KP1];   // [n][k]
__device__ __align__(16) __half g_Wo    [(size_t)HIDDEN * KP2];   // [n][k], cols reordered

// ---------------------------------------------------------------------------
// Helpers
// ---------------------------------------------------------------------------
__device__ __forceinline__ uint32_t smem_u32(const void* p) {
    uint32_t a;
    asm("{ .reg .u64 t; cvta.to.shared.u64 t, %1; cvt.u32.u64 %0, t; }" : "=r"(a) : "l"(p));
    return a;
}
__device__ __forceinline__ void cp16(uint32_t dst, const void* src, uint32_t sz) {
    asm volatile("cp.async.ca.shared.global [%0], [%1], 16, %2;" :: "r"(dst), "l"(src), "r"(sz) : "memory");
}
__device__ __forceinline__ void cp_commit() {
    asm volatile("cp.async.commit_group;" ::: "memory");
}
template <int N>
__device__ __forceinline__ void cp_wait() {
    asm volatile("cp.async.wait_group %0;" :: "n"(N) : "memory");
}
// fp16 inputs, fp32 accumulate
__device__ __forceinline__ void mma16(float& d0, float& d1, float& d2, float& d3,
                                      uint32_t a0, uint32_t a1, uint32_t a2, uint32_t a3,
                                      uint32_t b0, uint32_t b1) {
    asm volatile(
        "mma.sync.aligned.m16n8k16.row.col.f32.f16.f16.f32 "
        "{%0,%1,%2,%3}, {%4,%5,%6,%7}, {%8,%9}, {%0,%1,%2,%3};"
        : "+f"(d0), "+f"(d1), "+f"(d2), "+f"(d3)
        : "r"(a0), "r"(a1), "r"(a2), "r"(a3), "r"(b0), "r"(b1));
}

// SMEM layout (bytes), 3-stage ring (no WAR races: cp(s+2) never touches the
// buffer being computed (s) or gather-stored (s+1)):
//   [0, 3072)       gidx: 128 rows x 6 ints
//   [3072, +3*6144) A bufs: 128 rows x 24 halfs (16 cols + pad, conflict-free)
//   [21504, +3*12288) B bufs: 256 rows x 24 halfs
constexpr int GOFF_B  = 0;
constexpr int AOFF_B  = 3072;
constexpr int A_BUF_B = 128 * 24 * 2;            // 6144
constexpr int BOFF_B  = AOFF_B + 3 * A_BUF_B;    // 21504
constexpr int B_BUF_B = 256 * 24 * 2;            // 12288
constexpr int SMEM_BYTES = BOFF_B + 3 * B_BUF_B; // 58368

// ---------------------------------------------------------------------------
// Fused gather + fp16 HMMA GEMM: C[M,256] = epi( A[M,K] @ W[256,K]^T )
//   gathered chunk s: A[m][s*16..] = fp16(sum_j msg[graph[m,j]][s*16..])
//   feature chunk:    cp.async from Apad (pre-rounded fp16)
// MODE 0: C2h <- raw fp16, Ch <- relu fp16     (init; no gather)
// MODE 1: Ch <- relu(binput + raw) fp16        (rounds; all chunks gathered)
// MODE 2: Cf <- relu(raw + b_o[n]) fp32        (readout; chunks <16 gathered)
// ---------------------------------------------------------------------------
template <int MODE, int KT>
__global__ void __launch_bounds__(512, 1)
gemm_fused(const __half* __restrict__ msg,
           const int* __restrict__ graph,
           const __half* __restrict__ Apad, int ldah,
           const __half* __restrict__ Bt, int ldbh,
           const void* __restrict__ extra,
           __half* __restrict__ Ch, float* __restrict__ Cf,
           __half* __restrict__ C2h, int M) {
    extern __shared__ char smc[];
    int* sgidx = (int*)(smc + GOFF_B);
    const uint32_t sbase = smem_u32(smc);
    const int tid  = threadIdx.x;
    const int wid  = tid >> 5;
    const int lane = tid & 31;
    const int mBase = blockIdx.x * 128;
    const int warpM = (wid >> 3) * 64;
    const int warpN = (wid & 7) * 32;

    constexpr int FEAT0 = (MODE == 2) ? 16 : 0;
    auto gathered = [](int s) { return MODE == 1 || (MODE == 2 && s < 16); };

    const int grow = tid >> 2;   // 0..127 (gather row)
    const int gc   = tid & 3;    // 4-half slot within 16-col chunk

    if (MODE != 0) {
#pragma unroll
        for (int i = tid; i < 128 * MAX_NB; i += 512) {
            int gi = mBase * MAX_NB + i;
            sgidx[i] = (gi < M * MAX_NB) ? graph[gi] : 0;
        }
        __syncthreads();
    }

    uint2 u[6];   // held gather prefetch (6 x 4 halfs)

    auto issue_gather = [&](int s) {
#pragma unroll
        for (int j = 0; j < 6; ++j) {
            int idx = sgidx[grow * 6 + j];
            u[j] = __ldg((const uint2*)(msg + (size_t)idx * HIDDEN + s * BK + gc * 4));
        }
    };
    auto store_gather = [&](int s) {
        float f0 = 0.f, f1 = 0.f, f2 = 0.f, f3 = 0.f;
#pragma unroll
        for (int j = 0; j < 6; ++j) {
            float2 lo = __half22float2(*(const __half2*)&u[j].x);
            float2 hi = __half22float2(*(const __half2*)&u[j].y);
            f0 += lo.x; f1 += lo.y; f2 += hi.x; f3 += hi.y;
        }
        uint2 r;
        *(__half2*)&r.x = __floats2half2_rn(f0, f1);
        *(__half2*)&r.y = __floats2half2_rn(f2, f3);
        *(uint2*)(smc + AOFF_B + (s % 3) * A_BUF_B + (grow * 24 + gc * 4) * 2) = r;
    };
    auto cpA = [&](int s) {
        if (tid < 256) {
            int row = tid >> 1, h = tid & 1;
            int gm = mBase + row;
            const void* src = Apad + (size_t)gm * ldah + (s - FEAT0) * BK + h * 8;
            uint32_t dst = sbase + AOFF_B + (s % 3) * A_BUF_B + (row * 24 + h * 8) * 2;
            cp16(dst, src, (gm < M) ? 16u : 0u);
        }
    };
    auto cpB = [&](int s) {
        int row = tid >> 1, h = tid & 1;   // 512 threads -> 256 rows x 2
        const void* src = Bt + (size_t)row * ldbh + s * BK + h * 8;
        uint32_t dst = sbase + BOFF_B + (s % 3) * B_BUF_B + (row * 24 + h * 8) * 2;
        cp16(dst, src, 16u);
    };

    // --- prologue: chunks 0 and 1 ---
    if (gathered(0)) { issue_gather(0); store_gather(0); }
    else cpA(0);
    cpB(0); cp_commit();
    if (KT > 1) {
        if (gathered(1)) issue_gather(1);   // hold in regs; stored during s=0
        else cpA(1);
        cpB(1); cp_commit();
    }
    cp_wait<1>();
    __syncthreads();

    float acc[4][4][4];
#pragma unroll
    for (int a = 0; a < 4; ++a)
#pragma unroll
        for (int b = 0; b < 4; ++b)
#pragma unroll
            for (int c = 0; c < 4; ++c) acc[a][b][c] = 0.0f;

#pragma unroll 1
    for (int s = 0; s < KT; ++s) {
        const __half* bA = (const __half*)(smc + AOFF_B + (s % 3) * A_BUF_B);
        const __half* bB = (const __half*)(smc + BOFF_B + (s % 3) * B_BUF_B);
        const int k0 = (lane & 3) * 2;

        uint32_t afr[4][4];
#pragma unroll
        for (int mt = 0; mt < 4; ++mt) {
            const int r0 = warpM + mt * 16 + (lane >> 2);
            const int r1 = r0 + 8;
            afr[mt][0] = *(const uint32_t*)&bA[r0 * 24 + k0];
            afr[mt][1] = *(const uint32_t*)&bA[r1 * 24 + k0];
            afr[mt][2] = *(const uint32_t*)&bA[r0 * 24 + k0 + 8];
            afr[mt][3] = *(const uint32_t*)&bA[r1 * 24 + k0 + 8];
        }
#pragma unroll
        for (int nt = 0; nt < 4; ++nt) {
            const int nn = warpN + nt * 8 + (lane >> 2);
            uint32_t b0 = *(const uint32_t*)&bB[nn * 24 + k0];
            uint32_t b1 = *(const uint32_t*)&bB[nn * 24 + k0 + 8];
#pragma unroll
            for (int mt = 0; mt < 4; ++mt)
                mma16(acc[mt][nt][0], acc[mt][nt][1], acc[mt][nt][2], acc[mt][nt][3],
                      afr[mt][0], afr[mt][1], afr[mt][2], afr[mt][3], b0, b1);
        }

        // stage next: writes target bufs (s+1)%3 and (s+2)%3 — never s%3
        if (s + 1 < KT && gathered(s + 1)) store_gather(s + 1);
        if (s + 2 < KT) {
            if (gathered(s + 2)) issue_gather(s + 2);
            else cpA(s + 2);
            cpB(s + 2);
        }
        cp_commit();
        cp_wait<1>();
        __syncthreads();
    }

    // --- epilogue ---
#pragma unroll
    for (int mt = 0; mt < 4; ++mt) {
#pragma unroll
        for (int rg = 0; rg < 2; ++rg) {
            const int r = mBase + warpM + mt * 16 + (lane >> 2) + rg * 8;
            if (r < M) {
#pragma unroll
                for (int nt = 0; nt < 4; ++nt) {
                    const int col = warpN + nt * 8 + (lane & 3) * 2;
                    const size_t off = (size_t)r * HIDDEN + col;
                    float v0 = acc[mt][nt][rg * 2 + 0];
                    float v1 = acc[mt][nt][rg * 2 + 1];
                    if (MODE == 1) {
                        float2 e = __half22float2(*(const __half2*)((const __half*)extra + off));
                        v0 += e.x; v1 += e.y;
                    }
                    if (MODE == 2) {
                        const float* bo = (const float*)extra;
                        v0 += __ldg(bo + col);
                        v1 += __ldg(bo + col + 1);
                    }
                    if (MODE == 0)
                        *(__half2*)(C2h + off) = __floats2half2_rn(v0, v1);
                    v0 = fmaxf(v0, 0.0f); v1 = fmaxf(v1, 0.0f);
                    if (MODE == 2)
                        *(float2*)(Cf + off) = make_float2(v0, v1);
                    else
                        *(__half2*)(Ch + off) = __floats2half2_rn(v0, v1);
                }
            }
        }
    }
}

// ---------------------------------------------------------------------------
// Producers: fp16 conversion (rn) of all GEMM operands
// ---------------------------------------------------------------------------
__global__ void pad_fb_k(const float* __restrict__ in, __half* __restrict__ out) {
    size_t i = (size_t)blockIdx.x * blockDim.x + threadIdx.x;
    if (i >= (size_t)N_BONDS * KP0) return;
    int r = (int)(i / KP0), c = (int)(i % KP0);
    out[i] = (c < IN_FDIM) ? __float2half_rn(in[(size_t)r * IN_FDIM + c]) : __half(0.f);
}
__global__ void cv_wi_k(const float* __restrict__ W, __half* __restrict__ out) {
    int i = blockIdx.x * blockDim.x + threadIdx.x;
    if (i >= HIDDEN * KP0) return;
    int n = i / KP0, k = i % KP0;
    out[i] = (k < IN_FDIM) ? __float2half_rn(W[(size_t)n * IN_FDIM + k]) : __half(0.f);
}
__global__ void cv_wh_k(const float* __restrict__ W, __half* __restrict__ out) {
    int i = blockIdx.x * blockDim.x + threadIdx.x;
    if (i >= HIDDEN * KP1) return;
    out[i] = __float2half_rn(W[i]);
}
// Wo k-reorder to match A layout: [hidden(256) | atom(39) | pad]
__global__ void cv_wo_k(const float* __restrict__ W, __half* __restrict__ out) {
    int i = blockIdx.x * blockDim.x + threadIdx.x;
    if (i >= HIDDEN * KP2) return;
    int n = i / KP2, k = i % KP2;
    float v = 0.0f;
    if (k < 256) v = W[(size_t)n * OUT_FDIM + ATOM_FDIM + k];
    else if (k < OUT_FDIM) v = W[(size_t)n * OUT_FDIM + (k - 256)];
    out[i] = __float2half_rn(v);
}
__global__ void pad_afeat_k(const float* __restrict__ fatoms, __half* __restrict__ afeat) {
    int i = blockIdx.x * blockDim.x + threadIdx.x;
    if (i >= N_ATOMS * 64) return;
    int r = i / 64, c = i % 64;
    afeat[i] = (c < ATOM_FDIM) ? __float2half_rn(fatoms[(size_t)r * ATOM_FDIM + c]) : __half(0.f);
}

__global__ void pool_k(const float* __restrict__ atomh, float* __restrict__ out) {
    const int mol = blockIdx.x;
    const int n   = threadIdx.x;
    const float* base = atomh + (size_t)mol * APM * HIDDEN;
    float s = 0.0f;
#pragma unroll
    for (int i = 0; i < APM; ++i) s += base[(size_t)i * HIDDEN + n];
    out[(size_t)mol * HIDDEN + n] = s * (1.0f / (float)APM);
}

// ---------------------------------------------------------------------------
extern "C" void kernel_launch(void* const* d_in, const int* in_sizes, int n_in,
                              void* d_out, int out_size) {
    const float* fatoms = (const float*)d_in[0];
    const float* fbonds = (const float*)d_in[1];
    const int*   agraph = (const int*)  d_in[2];
    const int*   bgraph = (const int*)  d_in[3];
    const float* W_i = (const float*)d_in[5];
    const float* W_h = (const float*)d_in[6];
    const float* W_o = (const float*)d_in[7];
    const float* b_o = (const float*)d_in[8];
    float* out = (float*)d_out;

    __half *binput, *msg0, *msg1, *fbpad, *afeat, *Wi, *Wh, *Wo;
    float *atomh;
    cudaGetSymbolAddress((void**)&binput, g_binput);
    cudaGetSymbolAddress((void**)&msg0,   g_msg0);
    cudaGetSymbolAddress((void**)&msg1,   g_msg1);
    cudaGetSymbolAddress((void**)&atomh,  g_atomh);
    cudaGetSymbolAddress((void**)&fbpad,  g_fbpad);
    cudaGetSymbolAddress((void**)&afeat,  g_afeat);
    cudaGetSymbolAddress((void**)&Wi,     g_Wi);
    cudaGetSymbolAddress((void**)&Wh,     g_Wh);
    cudaGetSymbolAddress((void**)&Wo,     g_Wo);

    cudaFuncSetAttribute(gemm_fused<0, KP0 / BK>, cudaFuncAttributeMaxDynamicSharedMemorySize, SMEM_BYTES);
    cudaFuncSetAttribute(gemm_fused<1, KP1 / BK>, cudaFuncAttributeMaxDynamicSharedMemorySize, SMEM_BYTES);
    cudaFuncSetAttribute(gemm_fused<2, KP2 / BK>, cudaFuncAttributeMaxDynamicSharedMemorySize, SMEM_BYTES);

    // producers
    {
        size_t n = (size_t)N_BONDS * KP0;
        pad_fb_k<<<(unsigned)((n + 255) / 256), 256>>>(fbonds, fbpad);
        cv_wi_k<<<(HIDDEN * KP0 + 255) / 256, 256>>>(W_i, Wi);
        cv_wh_k<<<(HIDDEN * KP1 + 255) / 256, 256>>>(W_h, Wh);
        cv_wo_k<<<(HIDDEN * KP2 + 255) / 256, 256>>>(W_o, Wo);
        pad_afeat_k<<<(N_ATOMS * 64 + 255) / 256, 256>>>(fatoms, afeat);
    }

    const int tilesB = (N_BONDS + 127) / 128;
    const int tilesA = (N_ATOMS + 127) / 128;

    // init: binput(raw fp16) + msg0 = relu fp16
    gemm_fused<0, KP0 / BK><<<tilesB, 512, SMEM_BYTES>>>(
        nullptr, nullptr, fbpad, KP0, Wi, KP0,
        nullptr, msg0, nullptr, binput, N_BONDS);

    // 5 message-passing rounds (gather fused, fp16 msg traffic)
    __half* cur = msg0;
    __half* nxt = msg1;
    for (int r = 0; r < 5; ++r) {
        gemm_fused<1, KP1 / BK><<<tilesB, 512, SMEM_BYTES>>>(
            cur, bgraph, nullptr, 0, Wh, KP1,
            binput, nxt, nullptr, nullptr, N_BONDS);
        __half* t = cur; cur = nxt; nxt = t;
    }

    // atom readout (fp32 out for pooling)
    gemm_fused<2, KP2 / BK><<<tilesA, 512, SMEM_BYTES>>>(
        cur, agraph, afeat, 64, Wo, KP2,
        b_o, nullptr, atomh, nullptr, N_ATOMS);

    // mean pool
    pool_k<<<N_MOLS, 256>>>(atomh, out);
}